// round 13
// baseline (speedup 1.0000x reference)
#include <cuda_runtime.h>
#include <cuda_bf16.h>
#include <cuda_fp16.h>
#include <math.h>
#include <stdint.h>

#define Dd 512
#define Hh 512
#define Ff 2048
#define Ll 2
#define Ss 4
#define Pp 2
#define Tt 3
#define NEe 6
#define Gg 64
#define Bb 4096
#define NG 18

typedef __half fp16;

// ---------------- scratch (device globals; allocation-free)
__device__ __align__(16) fp16 g_wWin_h [2621440],  g_wWin_l [2621440];
__device__ __align__(16) fp16 g_wWc_h  [5242880],  g_wWc_l  [5242880];
__device__ float g_bc[20 * Hh];
__device__ __align__(16) fp16 g_wW1_h  [20971520], g_wW1_l  [20971520];
__device__ __align__(16) fp16 g_wW2_h  [20971520], g_wW2_l  [20971520];
__device__ __align__(16) fp16 g_wWout_h[2621440],  g_wWout_l[2621440];
__device__ __align__(16) fp16 g_wWf1_h [1572864],  g_wWf1_l [1572864];
__device__ __align__(16) fp16 g_wWf2_h [524288],   g_wWf2_l [524288];
__device__ __align__(16) fp16 g_x16 [6291456];
__device__ float g_h32 [37748736];
__device__ __align__(16) fp16 g_h16 [37748736];
__device__ float g_t232[37748736];
__device__ __align__(16) fp16 g_f16 [150994944];
__device__ float g_o32 [37748736];
__device__ float g_gh  [(size_t)Tt * Bb * Gg];
__device__ float g_gate[(size_t)Tt * Bb * NEe];
__device__ __align__(16) fp16 g_cat16 [6291456];
__device__ __align__(16) fp16 g_fuse16[4194304];

// ---------------- helpers
__device__ __forceinline__ void cp16(void* dst, const void* src) {
    uint32_t d;
    asm("{ .reg .u64 t; cvta.to.shared.u64 t, %1; cvt.u32.u64 %0, t; }" : "=r"(d) : "l"(dst));
    asm volatile("cp.async.cg.shared.global [%0], [%1], 16;" :: "r"(d), "l"(src) : "memory");
}
__device__ __forceinline__ void mma_f16(float* c, const uint32_t* a, const uint32_t* b) {
    asm volatile("mma.sync.aligned.m16n8k16.row.col.f32.f16.f16.f32 "
                 "{%0,%1,%2,%3}, {%4,%5,%6,%7}, {%8,%9}, {%0,%1,%2,%3};"
                 : "+f"(c[0]), "+f"(c[1]), "+f"(c[2]), "+f"(c[3])
                 : "r"(a[0]), "r"(a[1]), "r"(a[2]), "r"(a[3]), "r"(b[0]), "r"(b[1]));
}
__device__ __forceinline__ float warp_sum(float v) {
    v += __shfl_xor_sync(0xffffffffu, v, 16);
    v += __shfl_xor_sync(0xffffffffu, v, 8);
    v += __shfl_xor_sync(0xffffffffu, v, 4);
    v += __shfl_xor_sync(0xffffffffu, v, 2);
    v += __shfl_xor_sync(0xffffffffu, v, 1);
    return v;
}
__device__ __forceinline__ int expert_of_group(int g) {
    int task = g / NEe;
    int n = g % NEe;
    return (n < Ss) ? n : Ss + task * Pp + (n - Ss);
}

// ---------------- fp16x2 HMMA grouped GEMM — 128x128 tile, 3-stage swizzled pipeline
// A single fp16 plane [*,K]; W hi/lo fp16 planes [N,K]. acc += A*Wh; acc += A*Wl (pass-major).
#define PLANE_B 8192
#define STAGE_B 24576
#define TG_SMEM (3 * 24576)

template <int EPI, int OUT>   // EPI: 0 none, 1 gelu, 2 relu.  OUT: 0 f32, 1 fp16, 2 both
__global__ __launch_bounds__(256, 2)
void tgemm_kernel(const fp16* __restrict__ A, long aStride, int aMode,
                  const fp16* __restrict__ Whi, const fp16* __restrict__ Wlo, long wStride,
                  int wMode, int wMul, int wOff,
                  const float* __restrict__ bias, long bStride,
                  const float* __restrict__ Res, long resStride, int resMode,
                  float* __restrict__ C32, fp16* __restrict__ C16,
                  long cStride, int N, int K, int gBase)
{
    extern __shared__ char dsm[];

    const int g    = blockIdx.z + gBase;
    const int task = g / NEe;
    int wb = 0;
    if (wMode == 1) wb = expert_of_group(g);
    else if (wMode == 2) wb = g;
    const int widx = wb * wMul + wOff;
    const long aoff = (aMode == 1) ? (long)task * aStride : (aMode == 2 ? (long)g * aStride : 0);

    const int tid = threadIdx.x;
    const int blockRow = blockIdx.y * 128;
    const int blockCol = blockIdx.x * 128;

    const fp16* aP = A + aoff + (size_t)blockRow * K;
    const fp16* bH = Whi + (size_t)widx * wStride + (size_t)blockCol * K;
    const fp16* bL = Wlo + (size_t)widx * wStride + (size_t)blockCol * K;

    const int warp  = tid >> 5, lane = tid & 31;
    const int warpM = warp >> 2, warpN = warp & 3;     // 2 x 4 warp grid; 64x32 per warp
    const int grp   = lane >> 2, qp = lane & 3;

    const int lrow = tid >> 2;
    const int lseg = tid & 3;

    const int nch = K >> 5;

    const uint32_t so_h0 = (uint32_t)(lrow * 128 + ((lseg ^ (lrow & 7)) * 16));
    const uint32_t so_h1 = (uint32_t)(lrow * 128 + (((4 + lseg) ^ (lrow & 7)) * 16));

    auto load_chunk = [&](int kc, int s) {
        char* sb = dsm + s * STAGE_B;
        size_t kofs = (size_t)kc * 32 + (size_t)lseg * 8;
        size_t g0 = (size_t)lrow * K + kofs;
        size_t g1 = (size_t)(lrow + 64) * K + kofs;
        cp16(sb +             so_h0, aP + g0);
        cp16(sb +             so_h1, aP + g1);
        cp16(sb + PLANE_B   + so_h0, bH + g0);
        cp16(sb + PLANE_B   + so_h1, bH + g1);
        cp16(sb + 2*PLANE_B + so_h0, bL + g0);
        cp16(sb + 2*PLANE_B + so_h1, bL + g1);
        asm volatile("cp.async.commit_group;" ::: "memory");
    };

    float acc[4][4][4];
#pragma unroll
    for (int i = 0; i < 4; i++)
#pragma unroll
        for (int j = 0; j < 4; j++)
#pragma unroll
            for (int k = 0; k < 4; k++) acc[i][j][k] = 0.f;

    load_chunk(0, 0);
    load_chunk(1, 1);

    const uint32_t q4 = (uint32_t)(qp * 4);
    auto frago = [&](int row, int gran) -> uint32_t {
        int L = row & 63, hf = row >> 6;
        return (uint32_t)(L * 128 + (((hf * 4 + gran) ^ (L & 7)) * 16)) + q4;
    };

    for (int c = 0; c < nch; ++c) {
        if (c + 2 < nch) asm volatile("cp.async.wait_group 1;" ::: "memory");
        else             asm volatile("cp.async.wait_group 0;" ::: "memory");
        __syncthreads();
        if (c + 2 < nch) load_chunk(c + 2, (c + 2) % 3);

        const char* sb = dsm + (c % 3) * STAGE_B;
        const char* sA  = sb;
        const char* sBh = sb + PLANE_B;
        const char* sBl = sb + 2*PLANE_B;

#pragma unroll
        for (int kt = 0; kt < 2; ++kt) {
            const int gran = kt * 2;
            uint32_t Af[4][4], Bf[4][2], Blf[4][2];
#pragma unroll
            for (int mt = 0; mt < 4; ++mt) {
                int r0 = warpM * 64 + mt * 16 + grp;
                Af[mt][0] = *(const uint32_t*)(sA + frago(r0, gran));
                Af[mt][1] = *(const uint32_t*)(sA + frago(r0 + 8, gran));
                Af[mt][2] = *(const uint32_t*)(sA + frago(r0, gran + 1));
                Af[mt][3] = *(const uint32_t*)(sA + frago(r0 + 8, gran + 1));
            }
#pragma unroll
            for (int nt = 0; nt < 4; ++nt) {
                int n0 = warpN * 32 + nt * 8 + grp;
                uint32_t o0 = frago(n0, gran);
                uint32_t o1 = frago(n0, gran + 1);
                Bf[nt][0] = *(const uint32_t*)(sBh + o0);
                Bf[nt][1] = *(const uint32_t*)(sBh + o1);
                Blf[nt][0] = *(const uint32_t*)(sBl + o0);
                Blf[nt][1] = *(const uint32_t*)(sBl + o1);
            }
            // pass-major: 16 independent accumulators between dependent HMMAs
#pragma unroll
            for (int mt = 0; mt < 4; ++mt)
#pragma unroll
                for (int nt = 0; nt < 4; ++nt)
                    mma_f16(acc[mt][nt], Af[mt], Bf[nt]);
#pragma unroll
            for (int mt = 0; mt < 4; ++mt)
#pragma unroll
                for (int nt = 0; nt < 4; ++nt)
                    mma_f16(acc[mt][nt], Af[mt], Blf[nt]);
        }
    }
    __syncthreads();

    // ---- epilogue: regs -> smem f32 bounce -> coalesced gmem
    float* sbuf = reinterpret_cast<float*>(dsm);
#pragma unroll
    for (int mt = 0; mt < 4; ++mt) {
        int r0 = warpM * 64 + mt * 16 + grp;
#pragma unroll
        for (int nt = 0; nt < 4; ++nt) {
            int cb = warpN * 32 + nt * 8 + 2 * qp;
            sbuf[r0 * 129 + cb]       = acc[mt][nt][0];
            sbuf[r0 * 129 + cb + 1]   = acc[mt][nt][1];
            sbuf[(r0+8) * 129 + cb]   = acc[mt][nt][2];
            sbuf[(r0+8) * 129 + cb+1] = acc[mt][nt][3];
        }
    }
    __syncthreads();

    const size_t coff = (size_t)g * cStride;
    const size_t roff = Res ? ((resMode == 1) ? (size_t)task * resStride : (size_t)g * resStride) : 0;

#pragma unroll 4
    for (int it = 0; it < 64; ++it) {
        int idx = it * 256 + tid;
        int rr = idx >> 7, cc = idx & 127;
        int gcol = blockCol + cc;
        float v = sbuf[rr * 129 + cc];
        if (bias) v += bias[(size_t)widx * bStride + gcol];
        size_t rowoff = (size_t)(blockRow + rr) * N + gcol;
        if (Res) v += Res[roff + rowoff];
        if (EPI == 1)      v = 0.5f * v * (1.0f + erff(v * 0.70710678118654752440f));
        else if (EPI == 2) v = fmaxf(v, 0.f);
        size_t o = coff + rowoff;
        if (OUT != 1) C32[o] = v;
        if (OUT >= 1) C16[o] = __float2half_rn(v);
    }
}

// ---------------- attention fusion precompute: Wc = Wv@Wo -> fp16 hi/lo [N,K]
__global__ void wcomb_kernel(const float* __restrict__ Wv, const float* __restrict__ Wo,
                             fp16* __restrict__ hi, fp16* __restrict__ lo)
{
    __shared__ float tV[32][33];
    __shared__ float tO[32][33];
    const int z = blockIdx.z;
    const int n0 = blockIdx.x * 32, k0 = blockIdx.y * 32;
    const int tx = threadIdx.x, ty = threadIdx.y;
    const size_t base = (size_t)z * Hh * Hh;
    float acc[4] = {0.f, 0.f, 0.f, 0.f};
    for (int j0 = 0; j0 < Hh; j0 += 32) {
        for (int r = ty; r < 32; r += 8) {
            tV[r][tx] = Wv[base + (size_t)(k0 + r) * Hh + j0 + tx];
            tO[r][tx] = Wo[base + (size_t)(j0 + r) * Hh + n0 + tx];
        }
        __syncthreads();
#pragma unroll
        for (int jj = 0; jj < 32; ++jj) {
            float a = tV[tx][jj];
#pragma unroll
            for (int i = 0; i < 4; ++i)
                acc[i] += a * tO[jj][ty + i * 8];
        }
        __syncthreads();
    }
#pragma unroll
    for (int i = 0; i < 4; ++i) {
        int n = n0 + ty + i * 8;
        size_t o = base + (size_t)n * Hh + k0 + tx;
        float v = acc[i];
        fp16 h = __float2half_rn(v);
        hi[o] = h;
        lo[o] = __float2half_rn(v - __half2float(h));
    }
}

__global__ void bcomb_kernel(const float* __restrict__ bv, const float* __restrict__ Wo,
                             const float* __restrict__ bo, float* __restrict__ bc)
{
    const int z = blockIdx.x;
    const int n = threadIdx.x;
    const float* w = Wo + (size_t)z * Hh * Hh + n;
    const float* b = bv + (size_t)z * Hh;
    float s = bo[(size_t)z * Hh + n];
    for (int k = 0; k < Hh; ++k) s += b[k] * w[(size_t)k * Hh];
    bc[z * Hh + n] = s;
}

// ---------------- weight convert+transpose: f32 [K,N] -> fp16 hi/lo [N,K]
__global__ void wconv_kernel(const float* __restrict__ src, fp16* __restrict__ hi,
                             fp16* __restrict__ lo, int K, int N)
{
    __shared__ float tile[32][33];
    const size_t m = (size_t)blockIdx.z * K * N;
    const int n0 = blockIdx.x * 32, k0 = blockIdx.y * 32;
    const int tx = threadIdx.x, ty = threadIdx.y;
    for (int r = ty; r < 32; r += 8)
        tile[r][tx] = src[m + (size_t)(k0 + r) * N + n0 + tx];
    __syncthreads();
    for (int r = ty; r < 32; r += 8) {
        float v = tile[tx][r];
        size_t o = m + (size_t)(n0 + r) * K + k0 + tx;
        fp16 h = __float2half_rn(v);
        hi[o] = h;
        lo[o] = __float2half_rn(v - __half2float(h));
    }
}

// ---------------- elementwise f32 -> fp16
__global__ void split_kernel(const float* __restrict__ src, fp16* __restrict__ out, long n)
{
    long i = (long)blockIdx.x * blockDim.x + threadIdx.x;
    if (i < n) out[i] = __float2half_rn(src[i]);
}

// ---------------- fused LayerNorm; writes f32 (optional) + fp16 plane
__global__ void ln_kernel(float* __restrict__ Hbuf, fp16* __restrict__ H16,
                          const float* __restrict__ Add,
                          const float* __restrict__ gamma, const float* __restrict__ beta,
                          long gStride, int storeF32)
{
    const int g = blockIdx.y, row = blockIdx.x;
    const int e = expert_of_group(g);
    const long off = ((long)g * Bb + row) * Hh;
    float* h = Hbuf + off;
    const int t = threadIdx.x;

    float4 hv = *(const float4*)&h[t * 4];
    if (Add) {
        float4 av = *(const float4*)&Add[off + t * 4];
        hv.x += av.x; hv.y += av.y; hv.z += av.z; hv.w += av.w;
    }
    float s = hv.x + hv.y + hv.z + hv.w;
    __shared__ float sh[8];
    const int wid = t >> 5, lane = t & 31;
    s = warp_sum(s);
    if (lane == 0) sh[wid] = s;
    __syncthreads();
    float mean = (sh[0] + sh[1] + sh[2] + sh[3]) * (1.0f / Hh);
    float d0 = hv.x - mean, d1 = hv.y - mean, d2 = hv.z - mean, d3 = hv.w - mean;
    float ss = d0 * d0 + d1 * d1 + d2 * d2 + d3 * d3;
    ss = warp_sum(ss);
    if (lane == 0) sh[4 + wid] = ss;
    __syncthreads();
    float inv = rsqrtf((sh[4] + sh[5] + sh[6] + sh[7]) * (1.0f / Hh) + 1e-5f);

    const float* gm = gamma + (long)e * gStride;
    const float* bt = beta  + (long)e * gStride;
    float4 gv = *(const float4*)&gm[t * 4];
    float4 bv = *(const float4*)&bt[t * 4];
    float o0 = d0 * inv * gv.x + bv.x;
    float o1 = d1 * inv * gv.y + bv.y;
    float o2 = d2 * inv * gv.z + bv.z;
    float o3 = d3 * inv * gv.w + bv.w;
    if (storeF32) *(float4*)&h[t * 4] = make_float4(o0, o1, o2, o3);
    __half2 p01 = __floats2half2_rn(o0, o1);
    __half2 p23 = __floats2half2_rn(o2, o3);
    uint2 pk;
    pk.x = *(uint32_t*)&p01;
    pk.y = *(uint32_t*)&p23;
    *(uint2*)&H16[off + t * 4] = pk;
}

// ---------------- gate stage 1
__global__ void gate1_kernel(const float* __restrict__ x, const float* __restrict__ Wg1,
                             const float* __restrict__ bg1, float* __restrict__ gh)
{
    __shared__ float xs[Dd];
    const int i = blockIdx.y, b = blockIdx.x, t = threadIdx.x;
    const float* xr = x + ((long)i * Bb + b) * Dd;
    for (int k = t; k < Dd; k += 64) xs[k] = xr[k];
    __syncthreads();
    const float* w = Wg1 + (long)i * Dd * Gg + t;
    float s = bg1[i * Gg + t];
#pragma unroll 8
    for (int k = 0; k < Dd; ++k) s += xs[k] * w[(long)k * Gg];
    gh[((long)i * Bb + b) * Gg + t] = fmaxf(s, 0.f);
}

// ---------------- gate stage 2 + softmax
__global__ void gate2_kernel(const float* __restrict__ gh, const float* __restrict__ Wg2,
                             const float* __restrict__ bg2, float* __restrict__ gate)
{
    const int i = blockIdx.y;
    const int row = blockIdx.x * 4 + (threadIdx.x >> 5);
    const int lane = threadIdx.x & 31;
    const float* g1 = gh + ((long)i * Bb + row) * Gg;
    const float x0 = g1[lane], x1 = g1[lane + 32];
    const float* w = Wg2 + (long)i * Gg * NEe;
    float logits[NEe];
#pragma unroll
    for (int n = 0; n < NEe; n++) {
        float p = x0 * w[lane * NEe + n] + x1 * w[(lane + 32) * NEe + n];
        p = warp_sum(p);
        logits[n] = p + bg2[i * NEe + n];
    }
    float m = logits[0];
#pragma unroll
    for (int n = 1; n < NEe; n++) m = fmaxf(m, logits[n]);
    float ssum = 0.f;
#pragma unroll
    for (int n = 0; n < NEe; n++) { logits[n] = expf(logits[n] - m); ssum += logits[n]; }
    float rs = 1.0f / ssum;
    if (lane == 0) {
        float* gp = gate + ((long)i * Bb + row) * NEe;
#pragma unroll
        for (int n = 0; n < NEe; n++) gp[n] = logits[n] * rs;
    }
}

// ---------------- gated combine -> cat fp16
__global__ void combine_kernel(const float* __restrict__ o, const float* __restrict__ gate,
                               fp16* __restrict__ cat16)
{
    long idx = (long)blockIdx.x * blockDim.x + threadIdx.x;
    int d = (int)(idx % Dd);
    long bi = idx / Dd;
    int b = (int)(bi % Bb);
    int i = (int)(bi / Bb);
    const float* gp = gate + ((long)i * Bb + b) * NEe;
    float s = 0.f;
#pragma unroll
    for (int n = 0; n < NEe; n++)
        s += o[(((long)(i * NEe + n)) * Bb + b) * Hh + d] * gp[n];
    cat16[(long)b * (Tt * Dd) + i * Dd + d] = __float2half_rn(s);
}

// ---------------- launch
extern "C" void kernel_launch(void* const* d_in, const int* in_sizes, int n_in,
                              void* d_out, int out_size)
{
    const float* x    = (const float*)d_in[0];
    const float* Win  = (const float*)d_in[1];
    const float* b_in = (const float*)d_in[2];
    const float* Wv   = (const float*)d_in[3];
    const float* bv   = (const float*)d_in[4];
    const float* Wo   = (const float*)d_in[5];
    const float* bo   = (const float*)d_in[6];
    const float* ln1g = (const float*)d_in[7];
    const float* ln1b = (const float*)d_in[8];
    const float* W1   = (const float*)d_in[9];
    const float* b1   = (const float*)d_in[10];
    const float* W2   = (const float*)d_in[11];
    const float* b2   = (const float*)d_in[12];
    const float* ln2g = (const float*)d_in[13];
    const float* ln2b = (const float*)d_in[14];
    const float* lnfg = (const float*)d_in[15];
    const float* lnfb = (const float*)d_in[16];
    const float* Wout = (const float*)d_in[17];
    const float* bout = (const float*)d_in[18];
    const float* Wg1  = (const float*)d_in[19];
    const float* bg1  = (const float*)d_in[20];
    const float* Wg2  = (const float*)d_in[21];
    const float* bg2  = (const float*)d_in[22];
    const float* Wf1  = (const float*)d_in[23];
    const float* bf1  = (const float*)d_in[24];
    const float* Wf2  = (const float*)d_in[25];
    const float* bf2  = (const float*)d_in[26];

    fp16 *wWinH, *wWinL, *wWcH, *wWcL, *wW1H, *wW1L, *wW2H, *wW2L;
    fp16 *wWoutH, *wWoutL, *wWf1H, *wWf1L, *wWf2H, *wWf2L;
    fp16 *x16, *h16, *f16, *cat16, *fu16;
    float *h32, *t232, *o32, *gh, *gate, *bc;
    cudaGetSymbolAddress((void**)&wWinH, g_wWin_h);  cudaGetSymbolAddress((void**)&wWinL, g_wWin_l);
    cudaGetSymbolAddress((void**)&wWcH,  g_wWc_h);   cudaGetSymbolAddress((void**)&wWcL,  g_wWc_l);
    cudaGetSymbolAddress((void**)&wW1H,  g_wW1_h);   cudaGetSymbolAddress((void**)&wW1L,  g_wW1_l);
    cudaGetSymbolAddress((void**)&wW2H,  g_wW2_h);   cudaGetSymbolAddress((void**)&wW2L,  g_wW2_l);
    cudaGetSymbolAddress((void**)&wWoutH,g_wWout_h); cudaGetSymbolAddress((void**)&wWoutL,g_wWout_l);
    cudaGetSymbolAddress((void**)&wWf1H, g_wWf1_h);  cudaGetSymbolAddress((void**)&wWf1L, g_wWf1_l);
    cudaGetSymbolAddress((void**)&wWf2H, g_wWf2_h);  cudaGetSymbolAddress((void**)&wWf2L, g_wWf2_l);
    cudaGetSymbolAddress((void**)&x16, g_x16);
    cudaGetSymbolAddress((void**)&h16, g_h16);
    cudaGetSymbolAddress((void**)&f16, g_f16);
    cudaGetSymbolAddress((void**)&cat16, g_cat16);
    cudaGetSymbolAddress((void**)&fu16, g_fuse16);
    cudaGetSymbolAddress((void**)&h32, g_h32);  cudaGetSymbolAddress((void**)&t232, g_t232);
    cudaGetSymbolAddress((void**)&o32, g_o32);  cudaGetSymbolAddress((void**)&gh, g_gh);
    cudaGetSymbolAddress((void**)&gate, g_gate); cudaGetSymbolAddress((void**)&bc, g_bc);

    cudaFuncSetAttribute((const void*)tgemm_kernel<0,0>, cudaFuncAttributeMaxDynamicSharedMemorySize, TG_SMEM);
    cudaFuncSetAttribute((const void*)tgemm_kernel<0,1>, cudaFuncAttributeMaxDynamicSharedMemorySize, TG_SMEM);
    cudaFuncSetAttribute((const void*)tgemm_kernel<0,2>, cudaFuncAttributeMaxDynamicSharedMemorySize, TG_SMEM);
    cudaFuncSetAttribute((const void*)tgemm_kernel<1,1>, cudaFuncAttributeMaxDynamicSharedMemorySize, TG_SMEM);
    cudaFuncSetAttribute((const void*)tgemm_kernel<2,1>, cudaFuncAttributeMaxDynamicSharedMemorySize, TG_SMEM);

    const long GB = (long)Bb * Hh;
    const long GF = (long)Bb * Ff;
    dim3 blk(256);
    dim3 gHH(Hh / 128, Bb / 128, NG);
    dim3 gHHh(Hh / 128, Bb / 128, 9);
    dim3 gHF(Ff / 128, Bb / 128, NG);
    dim3 lnG(Bb, NG);
    dim3 cb(32, 8);

    // launch order keeps ncu capture (idx 3/4) on tgemm
    wconv_kernel<<<dim3(Hh/32, Dd/32, 10), cb>>>(Win,  wWinH,  wWinL,  Dd, Hh);
    long nx = (long)Tt * Bb * Dd;
    split_kernel<<<(unsigned)((nx + 255) / 256), 256>>>(x, x16, nx);
    wcomb_kernel<<<dim3(Hh/32, Hh/32, 20), cb>>>(Wv, Wo, wWcH, wWcL);
    tgemm_kernel<0,2><<<gHHh, blk, TG_SMEM>>>(x16, (long)Bb * Dd, 1,
        wWinH, wWinL, (long)Dd * Hh, 1, 1, 0, b_in, Hh,
        nullptr, 0, 0, h32, h16, GB, Hh, Dd, 0);
    tgemm_kernel<0,2><<<gHHh, blk, TG_SMEM>>>(x16, (long)Bb * Dd, 1,
        wWinH, wWinL, (long)Dd * Hh, 1, 1, 0, b_in, Hh,
        nullptr, 0, 0, h32, h16, GB, Hh, Dd, 9);
    bcomb_kernel<<<20, Hh>>>(bv, Wo, bo, bc);
    wconv_kernel<<<dim3(Ff/32, Hh/32, 20), cb>>>(W1,   wW1H,   wW1L,   Hh, Ff);
    wconv_kernel<<<dim3(Hh/32, Ff/32, 20), cb>>>(W2,   wW2H,   wW2L,   Ff, Hh);
    wconv_kernel<<<dim3(Dd/32, Hh/32, 10), cb>>>(Wout, wWoutH, wWoutL, Hh, Dd);
    wconv_kernel<<<dim3((2*Dd)/32, (Tt*Dd)/32, 1), cb>>>(Wf1, wWf1H, wWf1L, Tt*Dd, 2*Dd);
    wconv_kernel<<<dim3(Dd/32, (2*Dd)/32, 1), cb>>>(Wf2, wWf2H, wWf2L, 2*Dd, Dd);
    gate1_kernel<<<dim3(Bb, Tt), 64>>>(x, Wg1, bg1, gh);
    gate2_kernel<<<dim3(Bb / 4, Tt), 128>>>(gh, Wg2, bg2, gate);

    for (int l = 0; l < Ll; l++) {
        tgemm_kernel<0,0><<<gHH, blk, TG_SMEM>>>(h16, GB, 2,
            wWcH, wWcL, (long)Hh * Hh, 1, Ll, l, bc, Hh,
            nullptr, 0, 0, t232, nullptr, GB, Hh, Hh, 0);
        ln_kernel<<<lnG, 128>>>(h32, h16, t232, ln1g + (long)l * Hh, ln1b + (long)l * Hh, (long)Ll * Hh, 1);
        tgemm_kernel<1,1><<<gHF, blk, TG_SMEM>>>(h16, GB, 2,
            wW1H, wW1L, (long)Hh * Ff, 1, Ll, l, b1, Ff,
            nullptr, 0, 0, nullptr, f16, GF, Ff, Hh, 0);
        tgemm_kernel<0,0><<<gHH, blk, TG_SMEM>>>(f16, GF, 2,
            wW2H, wW2L, (long)Ff * Hh, 1, Ll, l, b2, Hh,
            nullptr, 0, 0, t232, nullptr, GB, Hh, Ff, 0);
        ln_kernel<<<lnG, 128>>>(h32, h16, t232, ln2g + (long)l * Hh, ln2b + (long)l * Hh, (long)Ll * Hh, 1);
    }

    ln_kernel<<<lnG, 128>>>(h32, h16, nullptr, lnfg, lnfb, (long)Hh, 0);

    tgemm_kernel<0,0><<<gHH, blk, TG_SMEM>>>(h16, GB, 2,
        wWoutH, wWoutL, (long)Hh * Dd, 1, 1, 0, bout, Dd,
        x, (long)Bb * Dd, 1, o32, nullptr, GB, Dd, Hh, 0);

    combine_kernel<<<(unsigned)(((long)Tt * Bb * Dd) / 256), 256>>>(o32, gate, cat16);

    tgemm_kernel<2,1><<<dim3((2*Dd)/128, Bb/128, 1), blk, TG_SMEM>>>(cat16, 0, 0,
        wWf1H, wWf1L, 0, 0, 1, 0, bf1, 0,
        nullptr, 0, 0, nullptr, fu16, 0, 2*Dd, Tt*Dd, 0);
    tgemm_kernel<0,0><<<dim3(Dd/128, Bb/128, 1), blk, TG_SMEM>>>(fu16, 0, 0,
        wWf2H, wWf2L, 0, 0, 1, 0, bf2, 0,
        nullptr, 0, 0, (float*)d_out, nullptr, 0, Dd, 2*Dd, 0);
}

// round 14
// speedup vs baseline: 1.0005x; 1.0005x over previous
#include <cuda_runtime.h>
#include <cuda_bf16.h>
#include <cuda_fp16.h>
#include <math.h>
#include <stdint.h>

#define Dd 512
#define Hh 512
#define Ff 2048
#define Ll 2
#define Ss 4
#define Pp 2
#define Tt 3
#define NEe 6
#define Gg 64
#define Bb 4096
#define NG 18

typedef __half fp16;

// ---------------- scratch (device globals; allocation-free)
__device__ __align__(16) fp16 g_wWin_h [2621440],  g_wWin_l [2621440];
__device__ __align__(16) fp16 g_wWc_h  [5242880],  g_wWc_l  [5242880];
__device__ float g_bc[20 * Hh];
__device__ __align__(16) fp16 g_wW1_h  [20971520], g_wW1_l  [20971520];
__device__ __align__(16) fp16 g_wW2_h  [20971520], g_wW2_l  [20971520];
__device__ __align__(16) fp16 g_wWout_h[2621440],  g_wWout_l[2621440];
__device__ __align__(16) fp16 g_wWf1_h [1572864],  g_wWf1_l [1572864];
__device__ __align__(16) fp16 g_wWf2_h [524288],   g_wWf2_l [524288];
__device__ __align__(16) fp16 g_x16 [6291456];
__device__ float g_h32 [37748736];
__device__ __align__(16) fp16 g_h16 [37748736];
__device__ float g_t232[37748736];
__device__ __align__(16) fp16 g_f16 [150994944];
__device__ float g_o32 [37748736];
__device__ float g_gh  [(size_t)Tt * Bb * Gg];
__device__ float g_gate[(size_t)Tt * Bb * NEe];
__device__ __align__(16) fp16 g_cat16 [6291456];
__device__ __align__(16) fp16 g_fuse16[4194304];

// ---------------- helpers
__device__ __forceinline__ void cp16(void* dst, const void* src) {
    uint32_t d;
    asm("{ .reg .u64 t; cvta.to.shared.u64 t, %1; cvt.u32.u64 %0, t; }" : "=r"(d) : "l"(dst));
    asm volatile("cp.async.cg.shared.global [%0], [%1], 16;" :: "r"(d), "l"(src) : "memory");
}
__device__ __forceinline__ void mma_f16(float* c, const uint32_t* a, const uint32_t* b) {
    asm volatile("mma.sync.aligned.m16n8k16.row.col.f32.f16.f16.f32 "
                 "{%0,%1,%2,%3}, {%4,%5,%6,%7}, {%8,%9}, {%0,%1,%2,%3};"
                 : "+f"(c[0]), "+f"(c[1]), "+f"(c[2]), "+f"(c[3])
                 : "r"(a[0]), "r"(a[1]), "r"(a[2]), "r"(a[3]), "r"(b[0]), "r"(b[1]));
}
__device__ __forceinline__ float warp_sum(float v) {
    v += __shfl_xor_sync(0xffffffffu, v, 16);
    v += __shfl_xor_sync(0xffffffffu, v, 8);
    v += __shfl_xor_sync(0xffffffffu, v, 4);
    v += __shfl_xor_sync(0xffffffffu, v, 2);
    v += __shfl_xor_sync(0xffffffffu, v, 1);
    return v;
}
__device__ __forceinline__ int expert_of_group(int g) {
    int task = g / NEe;
    int n = g % NEe;
    return (n < Ss) ? n : Ss + task * Pp + (n - Ss);
}

// ---------------- fp16x2 HMMA grouped GEMM — 128x128 tile, 3-stage swizzled pipeline
#define PLANE_B 8192
#define STAGE_B 24576
#define TG_SMEM (3 * 24576)

template <int EPI, int OUT>   // EPI: 0 none, 1 gelu, 2 relu.  OUT: 0 f32, 1 fp16, 2 both
__global__ __launch_bounds__(256, 2)
void tgemm_kernel(const fp16* __restrict__ A, long aStride, int aMode,
                  const fp16* __restrict__ Whi, const fp16* __restrict__ Wlo, long wStride,
                  int wMode, int wMul, int wOff,
                  const float* __restrict__ bias, long bStride,
                  const float* __restrict__ Res, long resStride, int resMode,
                  float* __restrict__ C32, fp16* __restrict__ C16,
                  long cStride, int N, int K, int gBase)
{
    extern __shared__ char dsm[];

    const int g    = blockIdx.z + gBase;
    const int task = g / NEe;
    int wb = 0;
    if (wMode == 1) wb = expert_of_group(g);
    else if (wMode == 2) wb = g;
    const int widx = wb * wMul + wOff;
    const long aoff = (aMode == 1) ? (long)task * aStride : (aMode == 2 ? (long)g * aStride : 0);

    const int tid = threadIdx.x;
    const int blockRow = blockIdx.y * 128;
    const int blockCol = blockIdx.x * 128;

    const fp16* aP = A + aoff + (size_t)blockRow * K;
    const fp16* bH = Whi + (size_t)widx * wStride + (size_t)blockCol * K;
    const fp16* bL = Wlo + (size_t)widx * wStride + (size_t)blockCol * K;

    const int warp  = tid >> 5, lane = tid & 31;
    const int warpM = warp >> 2, warpN = warp & 3;
    const int grp   = lane >> 2, qp = lane & 3;

    const int lrow = tid >> 2;
    const int lseg = tid & 3;

    const int nch = K >> 5;

    const uint32_t so_h0 = (uint32_t)(lrow * 128 + ((lseg ^ (lrow & 7)) * 16));
    const uint32_t so_h1 = (uint32_t)(lrow * 128 + (((4 + lseg) ^ (lrow & 7)) * 16));

    auto load_chunk = [&](int kc, int s) {
        char* sb = dsm + s * STAGE_B;
        size_t kofs = (size_t)kc * 32 + (size_t)lseg * 8;
        size_t g0 = (size_t)lrow * K + kofs;
        size_t g1 = (size_t)(lrow + 64) * K + kofs;
        cp16(sb +             so_h0, aP + g0);
        cp16(sb +             so_h1, aP + g1);
        cp16(sb + PLANE_B   + so_h0, bH + g0);
        cp16(sb + PLANE_B   + so_h1, bH + g1);
        cp16(sb + 2*PLANE_B + so_h0, bL + g0);
        cp16(sb + 2*PLANE_B + so_h1, bL + g1);
        asm volatile("cp.async.commit_group;" ::: "memory");
    };

    float acc[4][4][4];
#pragma unroll
    for (int i = 0; i < 4; i++)
#pragma unroll
        for (int j = 0; j < 4; j++)
#pragma unroll
            for (int k = 0; k < 4; k++) acc[i][j][k] = 0.f;

    load_chunk(0, 0);
    load_chunk(1, 1);

    const uint32_t q4 = (uint32_t)(qp * 4);
    auto frago = [&](int row, int gran) -> uint32_t {
        int L = row & 63, hf = row >> 6;
        return (uint32_t)(L * 128 + (((hf * 4 + gran) ^ (L & 7)) * 16)) + q4;
    };

    for (int c = 0; c < nch; ++c) {
        if (c + 2 < nch) asm volatile("cp.async.wait_group 1;" ::: "memory");
        else             asm volatile("cp.async.wait_group 0;" ::: "memory");
        __syncthreads();
        if (c + 2 < nch) load_chunk(c + 2, (c + 2) % 3);

        const char* sb = dsm + (c % 3) * STAGE_B;
        const char* sA  = sb;
        const char* sBh = sb + PLANE_B;
        const char* sBl = sb + 2*PLANE_B;

#pragma unroll
        for (int kt = 0; kt < 2; ++kt) {
            const int gran = kt * 2;
            uint32_t Af[4][4], Bf[4][2], Blf[4][2];
#pragma unroll
            for (int mt = 0; mt < 4; ++mt) {
                int r0 = warpM * 64 + mt * 16 + grp;
                Af[mt][0] = *(const uint32_t*)(sA + frago(r0, gran));
                Af[mt][1] = *(const uint32_t*)(sA + frago(r0 + 8, gran));
                Af[mt][2] = *(const uint32_t*)(sA + frago(r0, gran + 1));
                Af[mt][3] = *(const uint32_t*)(sA + frago(r0 + 8, gran + 1));
            }
#pragma unroll
            for (int nt = 0; nt < 4; ++nt) {
                int n0 = warpN * 32 + nt * 8 + grp;
                uint32_t o0 = frago(n0, gran);
                uint32_t o1 = frago(n0, gran + 1);
                Bf[nt][0] = *(const uint32_t*)(sBh + o0);
                Bf[nt][1] = *(const uint32_t*)(sBh + o1);
                Blf[nt][0] = *(const uint32_t*)(sBl + o0);
                Blf[nt][1] = *(const uint32_t*)(sBl + o1);
            }
#pragma unroll
            for (int mt = 0; mt < 4; ++mt)
#pragma unroll
                for (int nt = 0; nt < 4; ++nt)
                    mma_f16(acc[mt][nt], Af[mt], Bf[nt]);
#pragma unroll
            for (int mt = 0; mt < 4; ++mt)
#pragma unroll
                for (int nt = 0; nt < 4; ++nt)
                    mma_f16(acc[mt][nt], Af[mt], Blf[nt]);
        }
    }
    __syncthreads();

    // ---- epilogue
    float* sbuf = reinterpret_cast<float*>(dsm);
#pragma unroll
    for (int mt = 0; mt < 4; ++mt) {
        int r0 = warpM * 64 + mt * 16 + grp;
#pragma unroll
        for (int nt = 0; nt < 4; ++nt) {
            int cb = warpN * 32 + nt * 8 + 2 * qp;
            sbuf[r0 * 129 + cb]       = acc[mt][nt][0];
            sbuf[r0 * 129 + cb + 1]   = acc[mt][nt][1];
            sbuf[(r0+8) * 129 + cb]   = acc[mt][nt][2];
            sbuf[(r0+8) * 129 + cb+1] = acc[mt][nt][3];
        }
    }
    __syncthreads();

    const size_t coff = (size_t)g * cStride;
    const size_t roff = Res ? ((resMode == 1) ? (size_t)task * resStride : (size_t)g * resStride) : 0;

#pragma unroll 4
    for (int it = 0; it < 64; ++it) {
        int idx = it * 256 + tid;
        int rr = idx >> 7, cc = idx & 127;
        int gcol = blockCol + cc;
        float v = sbuf[rr * 129 + cc];
        if (bias) v += bias[(size_t)widx * bStride + gcol];
        size_t rowoff = (size_t)(blockRow + rr) * N + gcol;
        if (Res) v += Res[roff + rowoff];
        if (EPI == 1)      v = 0.5f * v * (1.0f + erff(v * 0.70710678118654752440f));
        else if (EPI == 2) v = fmaxf(v, 0.f);
        size_t o = coff + rowoff;
        if (OUT != 1) C32[o] = v;
        if (OUT >= 1) C16[o] = __float2half_rn(v);
    }
}

// ---------------- attention fusion precompute: Wc = Wv@Wo -> fp16 hi/lo [N,K]
__global__ void wcomb_kernel(const float* __restrict__ Wv, const float* __restrict__ Wo,
                             fp16* __restrict__ hi, fp16* __restrict__ lo)
{
    __shared__ float tV[32][33];
    __shared__ float tO[32][33];
    const int z = blockIdx.z;
    const int n0 = blockIdx.x * 32, k0 = blockIdx.y * 32;
    const int tx = threadIdx.x, ty = threadIdx.y;
    const size_t base = (size_t)z * Hh * Hh;
    float acc[4] = {0.f, 0.f, 0.f, 0.f};
    for (int j0 = 0; j0 < Hh; j0 += 32) {
        for (int r = ty; r < 32; r += 8) {
            tV[r][tx] = Wv[base + (size_t)(k0 + r) * Hh + j0 + tx];
            tO[r][tx] = Wo[base + (size_t)(j0 + r) * Hh + n0 + tx];
        }
        __syncthreads();
#pragma unroll
        for (int jj = 0; jj < 32; ++jj) {
            float a = tV[tx][jj];
#pragma unroll
            for (int i = 0; i < 4; ++i)
                acc[i] += a * tO[jj][ty + i * 8];
        }
        __syncthreads();
    }
#pragma unroll
    for (int i = 0; i < 4; ++i) {
        int n = n0 + ty + i * 8;
        size_t o = base + (size_t)n * Hh + k0 + tx;
        float v = acc[i];
        fp16 h = __float2half_rn(v);
        hi[o] = h;
        lo[o] = __float2half_rn(v - __half2float(h));
    }
}

__global__ void bcomb_kernel(const float* __restrict__ bv, const float* __restrict__ Wo,
                             const float* __restrict__ bo, float* __restrict__ bc)
{
    const int z = blockIdx.x;
    const int n = threadIdx.x;
    const float* w = Wo + (size_t)z * Hh * Hh + n;
    const float* b = bv + (size_t)z * Hh;
    float s = bo[(size_t)z * Hh + n];
    for (int k = 0; k < Hh; ++k) s += b[k] * w[(size_t)k * Hh];
    bc[z * Hh + n] = s;
}

// ---------------- weight convert+transpose: f32 [K,N] -> fp16 hi/lo [N,K]
__global__ void wconv_kernel(const float* __restrict__ src, fp16* __restrict__ hi,
                             fp16* __restrict__ lo, int K, int N)
{
    __shared__ float tile[32][33];
    const size_t m = (size_t)blockIdx.z * K * N;
    const int n0 = blockIdx.x * 32, k0 = blockIdx.y * 32;
    const int tx = threadIdx.x, ty = threadIdx.y;
    for (int r = ty; r < 32; r += 8)
        tile[r][tx] = src[m + (size_t)(k0 + r) * N + n0 + tx];
    __syncthreads();
    for (int r = ty; r < 32; r += 8) {
        float v = tile[tx][r];
        size_t o = m + (size_t)(n0 + r) * K + k0 + tx;
        fp16 h = __float2half_rn(v);
        hi[o] = h;
        lo[o] = __float2half_rn(v - __half2float(h));
    }
}

// ---------------- elementwise f32 -> fp16
__global__ void split_kernel(const float* __restrict__ src, fp16* __restrict__ out, long n)
{
    long i = (long)blockIdx.x * blockDim.x + threadIdx.x;
    if (i < n) out[i] = __float2half_rn(src[i]);
}

// ---------------- fused LayerNorm; reads In (f32), writes OutF32 (optional) + fp16 plane
__global__ void ln_kernel(const float* __restrict__ In, float* __restrict__ OutF32,
                          fp16* __restrict__ Out16,
                          const float* __restrict__ gamma, const float* __restrict__ beta,
                          long gStride, int storeF32)
{
    const int g = blockIdx.y, row = blockIdx.x;
    const int e = expert_of_group(g);
    const long off = ((long)g * Bb + row) * Hh;
    const int t = threadIdx.x;

    float4 hv = *(const float4*)&In[off + t * 4];
    float s = hv.x + hv.y + hv.z + hv.w;
    __shared__ float sh[8];
    const int wid = t >> 5, lane = t & 31;
    s = warp_sum(s);
    if (lane == 0) sh[wid] = s;
    __syncthreads();
    float mean = (sh[0] + sh[1] + sh[2] + sh[3]) * (1.0f / Hh);
    float d0 = hv.x - mean, d1 = hv.y - mean, d2 = hv.z - mean, d3 = hv.w - mean;
    float ss = d0 * d0 + d1 * d1 + d2 * d2 + d3 * d3;
    ss = warp_sum(ss);
    if (lane == 0) sh[4 + wid] = ss;
    __syncthreads();
    float inv = rsqrtf((sh[4] + sh[5] + sh[6] + sh[7]) * (1.0f / Hh) + 1e-5f);

    const float* gm = gamma + (long)e * gStride;
    const float* bt = beta  + (long)e * gStride;
    float4 gv = *(const float4*)&gm[t * 4];
    float4 bv = *(const float4*)&bt[t * 4];
    float o0 = d0 * inv * gv.x + bv.x;
    float o1 = d1 * inv * gv.y + bv.y;
    float o2 = d2 * inv * gv.z + bv.z;
    float o3 = d3 * inv * gv.w + bv.w;
    if (storeF32) *(float4*)&OutF32[off + t * 4] = make_float4(o0, o1, o2, o3);
    __half2 p01 = __floats2half2_rn(o0, o1);
    __half2 p23 = __floats2half2_rn(o2, o3);
    uint2 pk;
    pk.x = *(uint32_t*)&p01;
    pk.y = *(uint32_t*)&p23;
    *(uint2*)&Out16[off + t * 4] = pk;
}

// ---------------- gate stage 1
__global__ void gate1_kernel(const float* __restrict__ x, const float* __restrict__ Wg1,
                             const float* __restrict__ bg1, float* __restrict__ gh)
{
    __shared__ float xs[Dd];
    const int i = blockIdx.y, b = blockIdx.x, t = threadIdx.x;
    const float* xr = x + ((long)i * Bb + b) * Dd;
    for (int k = t; k < Dd; k += 64) xs[k] = xr[k];
    __syncthreads();
    const float* w = Wg1 + (long)i * Dd * Gg + t;
    float s = bg1[i * Gg + t];
#pragma unroll 8
    for (int k = 0; k < Dd; ++k) s += xs[k] * w[(long)k * Gg];
    gh[((long)i * Bb + b) * Gg + t] = fmaxf(s, 0.f);
}

// ---------------- gate stage 2 + softmax
__global__ void gate2_kernel(const float* __restrict__ gh, const float* __restrict__ Wg2,
                             const float* __restrict__ bg2, float* __restrict__ gate)
{
    const int i = blockIdx.y;
    const int row = blockIdx.x * 4 + (threadIdx.x >> 5);
    const int lane = threadIdx.x & 31;
    const float* g1 = gh + ((long)i * Bb + row) * Gg;
    const float x0 = g1[lane], x1 = g1[lane + 32];
    const float* w = Wg2 + (long)i * Gg * NEe;
    float logits[NEe];
#pragma unroll
    for (int n = 0; n < NEe; n++) {
        float p = x0 * w[lane * NEe + n] + x1 * w[(lane + 32) * NEe + n];
        p = warp_sum(p);
        logits[n] = p + bg2[i * NEe + n];
    }
    float m = logits[0];
#pragma unroll
    for (int n = 1; n < NEe; n++) m = fmaxf(m, logits[n]);
    float ssum = 0.f;
#pragma unroll
    for (int n = 0; n < NEe; n++) { logits[n] = expf(logits[n] - m); ssum += logits[n]; }
    float rs = 1.0f / ssum;
    if (lane == 0) {
        float* gp = gate + ((long)i * Bb + row) * NEe;
#pragma unroll
        for (int n = 0; n < NEe; n++) gp[n] = logits[n] * rs;
    }
}

// ---------------- gated combine -> cat fp16
__global__ void combine_kernel(const float* __restrict__ o, const float* __restrict__ gate,
                               fp16* __restrict__ cat16)
{
    long idx = (long)blockIdx.x * blockDim.x + threadIdx.x;
    int d = (int)(idx % Dd);
    long bi = idx / Dd;
    int b = (int)(bi % Bb);
    int i = (int)(bi / Bb);
    const float* gp = gate + ((long)i * Bb + b) * NEe;
    float s = 0.f;
#pragma unroll
    for (int n = 0; n < NEe; n++)
        s += o[(((long)(i * NEe + n)) * Bb + b) * Hh + d] * gp[n];
    cat16[(long)b * (Tt * Dd) + i * Dd + d] = __float2half_rn(s);
}

// ---------------- launch
extern "C" void kernel_launch(void* const* d_in, const int* in_sizes, int n_in,
                              void* d_out, int out_size)
{
    const float* x    = (const float*)d_in[0];
    const float* Win  = (const float*)d_in[1];
    const float* b_in = (const float*)d_in[2];
    const float* Wv   = (const float*)d_in[3];
    const float* bv   = (const float*)d_in[4];
    const float* Wo   = (const float*)d_in[5];
    const float* bo   = (const float*)d_in[6];
    const float* ln1g = (const float*)d_in[7];
    const float* ln1b = (const float*)d_in[8];
    const float* W1   = (const float*)d_in[9];
    const float* b1   = (const float*)d_in[10];
    const float* W2   = (const float*)d_in[11];
    const float* b2   = (const float*)d_in[12];
    const float* ln2g = (const float*)d_in[13];
    const float* ln2b = (const float*)d_in[14];
    const float* lnfg = (const float*)d_in[15];
    const float* lnfb = (const float*)d_in[16];
    const float* Wout = (const float*)d_in[17];
    const float* bout = (const float*)d_in[18];
    const float* Wg1  = (const float*)d_in[19];
    const float* bg1  = (const float*)d_in[20];
    const float* Wg2  = (const float*)d_in[21];
    const float* bg2  = (const float*)d_in[22];
    const float* Wf1  = (const float*)d_in[23];
    const float* bf1  = (const float*)d_in[24];
    const float* Wf2  = (const float*)d_in[25];
    const float* bf2  = (const float*)d_in[26];

    fp16 *wWinH, *wWinL, *wWcH, *wWcL, *wW1H, *wW1L, *wW2H, *wW2L;
    fp16 *wWoutH, *wWoutL, *wWf1H, *wWf1L, *wWf2H, *wWf2L;
    fp16 *x16, *h16, *f16, *cat16, *fu16;
    float *h32, *t232, *o32, *gh, *gate, *bc;
    cudaGetSymbolAddress((void**)&wWinH, g_wWin_h);  cudaGetSymbolAddress((void**)&wWinL, g_wWin_l);
    cudaGetSymbolAddress((void**)&wWcH,  g_wWc_h);   cudaGetSymbolAddress((void**)&wWcL,  g_wWc_l);
    cudaGetSymbolAddress((void**)&wW1H,  g_wW1_h);   cudaGetSymbolAddress((void**)&wW1L,  g_wW1_l);
    cudaGetSymbolAddress((void**)&wW2H,  g_wW2_h);   cudaGetSymbolAddress((void**)&wW2L,  g_wW2_l);
    cudaGetSymbolAddress((void**)&wWoutH,g_wWout_h); cudaGetSymbolAddress((void**)&wWoutL,g_wWout_l);
    cudaGetSymbolAddress((void**)&wWf1H, g_wWf1_h);  cudaGetSymbolAddress((void**)&wWf1L, g_wWf1_l);
    cudaGetSymbolAddress((void**)&wWf2H, g_wWf2_h);  cudaGetSymbolAddress((void**)&wWf2L, g_wWf2_l);
    cudaGetSymbolAddress((void**)&x16, g_x16);
    cudaGetSymbolAddress((void**)&h16, g_h16);
    cudaGetSymbolAddress((void**)&f16, g_f16);
    cudaGetSymbolAddress((void**)&cat16, g_cat16);
    cudaGetSymbolAddress((void**)&fu16, g_fuse16);
    cudaGetSymbolAddress((void**)&h32, g_h32);  cudaGetSymbolAddress((void**)&t232, g_t232);
    cudaGetSymbolAddress((void**)&o32, g_o32);  cudaGetSymbolAddress((void**)&gh, g_gh);
    cudaGetSymbolAddress((void**)&gate, g_gate); cudaGetSymbolAddress((void**)&bc, g_bc);

    cudaFuncSetAttribute((const void*)tgemm_kernel<0,0>, cudaFuncAttributeMaxDynamicSharedMemorySize, TG_SMEM);
    cudaFuncSetAttribute((const void*)tgemm_kernel<0,1>, cudaFuncAttributeMaxDynamicSharedMemorySize, TG_SMEM);
    cudaFuncSetAttribute((const void*)tgemm_kernel<0,2>, cudaFuncAttributeMaxDynamicSharedMemorySize, TG_SMEM);
    cudaFuncSetAttribute((const void*)tgemm_kernel<1,1>, cudaFuncAttributeMaxDynamicSharedMemorySize, TG_SMEM);
    cudaFuncSetAttribute((const void*)tgemm_kernel<2,1>, cudaFuncAttributeMaxDynamicSharedMemorySize, TG_SMEM);

    const long GB = (long)Bb * Hh;
    const long GF = (long)Bb * Ff;
    dim3 blk(256);
    dim3 gHH(Hh / 128, Bb / 128, NG);
    dim3 gHHh(Hh / 128, Bb / 128, 9);
    dim3 gHF(Ff / 128, Bb / 128, NG);
    dim3 lnG(Bb, NG);
    dim3 cb(32, 8);

    // capture stream (whatever stream kernel_launch is invoked on = legacy default here)
    cudaStream_t s0 = 0;
    cudaStream_t s2;
    cudaStreamCreateWithFlags(&s2, cudaStreamNonBlocking);
    cudaEvent_t eFork, eJoin;
    cudaEventCreateWithFlags(&eFork, cudaEventDisableTiming);
    cudaEventCreateWithFlags(&eJoin, cudaEventDisableTiming);

    // fork: side stream handles prepass not needed by the input-projection GEMM
    cudaEventRecord(eFork, s0);
    cudaStreamWaitEvent(s2, eFork, 0);

    // main stream: deps of input GEMM, then input GEMM
    wconv_kernel<<<dim3(Hh/32, Dd/32, 10), cb, 0, s0>>>(Win, wWinH, wWinL, Dd, Hh);
    long nx = (long)Tt * Bb * Dd;
    split_kernel<<<(unsigned)((nx + 255) / 256), 256, 0, s0>>>(x, x16, nx);
    tgemm_kernel<0,2><<<gHHh, blk, TG_SMEM, s0>>>(x16, (long)Bb * Dd, 1,
        wWinH, wWinL, (long)Dd * Hh, 1, 1, 0, b_in, Hh,
        nullptr, 0, 0, h32, h16, GB, Hh, Dd, 0);
    tgemm_kernel<0,2><<<gHHh, blk, TG_SMEM, s0>>>(x16, (long)Bb * Dd, 1,
        wWinH, wWinL, (long)Dd * Hh, 1, 1, 0, b_in, Hh,
        nullptr, 0, 0, h32, h16, GB, Hh, Dd, 9);

    // side stream: all remaining prepass (overlaps the input GEMM)
    wcomb_kernel<<<dim3(Hh/32, Hh/32, 20), cb, 0, s2>>>(Wv, Wo, wWcH, wWcL);
    bcomb_kernel<<<20, Hh, 0, s2>>>(bv, Wo, bo, bc);
    wconv_kernel<<<dim3(Ff/32, Hh/32, 20), cb, 0, s2>>>(W1,   wW1H,   wW1L,   Hh, Ff);
    wconv_kernel<<<dim3(Hh/32, Ff/32, 20), cb, 0, s2>>>(W2,   wW2H,   wW2L,   Ff, Hh);
    wconv_kernel<<<dim3(Dd/32, Hh/32, 10), cb, 0, s2>>>(Wout, wWoutH, wWoutL, Hh, Dd);
    wconv_kernel<<<dim3((2*Dd)/32, (Tt*Dd)/32, 1), cb, 0, s2>>>(Wf1, wWf1H, wWf1L, Tt*Dd, 2*Dd);
    wconv_kernel<<<dim3(Dd/32, (2*Dd)/32, 1), cb, 0, s2>>>(Wf2, wWf2H, wWf2L, 2*Dd, Dd);
    gate1_kernel<<<dim3(Bb, Tt), 64, 0, s2>>>(x, Wg1, bg1, gh);
    gate2_kernel<<<dim3(Bb / 4, Tt), 128, 0, s2>>>(gh, Wg2, bg2, gate);
    cudaEventRecord(eJoin, s2);
    cudaStreamWaitEvent(s0, eJoin, 0);

    for (int l = 0; l < Ll; l++) {
        // fused attention + residual: t232 = h + (h @ Wc + bc)
        tgemm_kernel<0,0><<<gHH, blk, TG_SMEM, s0>>>(h16, GB, 2,
            wWcH, wWcL, (long)Hh * Hh, 1, Ll, l, bc, Hh,
            h32, GB, 2, t232, nullptr, GB, Hh, Hh, 0);
        ln_kernel<<<lnG, 128, 0, s0>>>(t232, h32, h16, ln1g + (long)l * Hh, ln1b + (long)l * Hh, (long)Ll * Hh, 1);
        tgemm_kernel<1,1><<<gHF, blk, TG_SMEM, s0>>>(h16, GB, 2,
            wW1H, wW1L, (long)Hh * Ff, 1, Ll, l, b1, Ff,
            nullptr, 0, 0, nullptr, f16, GF, Ff, Hh, 0);
        // fused FFN + residual: t232 = h + (f @ W2 + b2)
        tgemm_kernel<0,0><<<gHH, blk, TG_SMEM, s0>>>(f16, GF, 2,
            wW2H, wW2L, (long)Ff * Hh, 1, Ll, l, b2, Hh,
            h32, GB, 2, t232, nullptr, GB, Hh, Ff, 0);
        ln_kernel<<<lnG, 128, 0, s0>>>(t232, h32, h16, ln2g + (long)l * Hh, ln2b + (long)l * Hh, (long)Ll * Hh, 1);
    }

    // final norm (input = h32, no residual; f32 output dead)
    ln_kernel<<<lnG, 128, 0, s0>>>(h32, h32, h16, lnfg, lnfb, (long)Hh, 0);

    tgemm_kernel<0,0><<<gHH, blk, TG_SMEM, s0>>>(h16, GB, 2,
        wWoutH, wWoutL, (long)Hh * Dd, 1, 1, 0, bout, Dd,
        x, (long)Bb * Dd, 1, o32, nullptr, GB, Dd, Hh, 0);

    combine_kernel<<<(unsigned)(((long)Tt * Bb * Dd) / 256), 256, 0, s0>>>(o32, gate, cat16);

    tgemm_kernel<2,1><<<dim3((2*Dd)/128, Bb/128, 1), blk, TG_SMEM, s0>>>(cat16, 0, 0,
        wWf1H, wWf1L, 0, 0, 1, 0, bf1, 0,
        nullptr, 0, 0, nullptr, fu16, 0, 2*Dd, Tt*Dd, 0);
    tgemm_kernel<0,0><<<dim3(Dd/128, Bb/128, 1), blk, TG_SMEM, s0>>>(fu16, 0, 0,
        wWf2H, wWf2L, 0, 0, 1, 0, bf2, 0,
        nullptr, 0, 0, (float*)d_out, nullptr, 0, Dd, 2*Dd, 0);

    cudaEventDestroy(eFork);
    cudaEventDestroy(eJoin);
    cudaStreamDestroy(s2);
}

// round 15
// speedup vs baseline: 1.4490x; 1.4482x over previous
#include <cuda_runtime.h>
#include <cuda_bf16.h>
#include <cuda_fp16.h>
#include <math.h>
#include <stdint.h>

#define Dd 512
#define Hh 512
#define Ff 2048
#define Ll 2
#define Ss 4
#define Pp 2
#define Tt 3
#define NEe 6
#define Gg 64
#define Bb 4096
#define NG 18

typedef __half fp16;

// ---------------- scratch (device globals; allocation-free)
__device__ __align__(16) fp16 g_wWin [2621440];
__device__ __align__(16) fp16 g_wWc  [5242880];
__device__ float g_bc[20 * Hh];
__device__ __align__(16) fp16 g_wW1  [20971520];
__device__ __align__(16) fp16 g_wW2  [20971520];
__device__ __align__(16) fp16 g_wWout[2621440];
__device__ __align__(16) fp16 g_wWf1 [1572864];
__device__ __align__(16) fp16 g_wWf2 [524288];
__device__ __align__(16) fp16 g_x16 [6291456];
__device__ float g_h32 [37748736];
__device__ __align__(16) fp16 g_h16 [37748736];
__device__ float g_t232[37748736];
__device__ __align__(16) fp16 g_f16 [150994944];
__device__ float g_o32 [37748736];
__device__ float g_gh  [(size_t)Tt * Bb * Gg];
__device__ float g_gate[(size_t)Tt * Bb * NEe];
__device__ __align__(16) fp16 g_cat16 [6291456];
__device__ __align__(16) fp16 g_fuse16[4194304];

// ---------------- helpers
__device__ __forceinline__ void cp16(void* dst, const void* src) {
    uint32_t d;
    asm("{ .reg .u64 t; cvta.to.shared.u64 t, %1; cvt.u32.u64 %0, t; }" : "=r"(d) : "l"(dst));
    asm volatile("cp.async.cg.shared.global [%0], [%1], 16;" :: "r"(d), "l"(src) : "memory");
}
__device__ __forceinline__ void mma_f16(float* c, const uint32_t* a, const uint32_t* b) {
    asm volatile("mma.sync.aligned.m16n8k16.row.col.f32.f16.f16.f32 "
                 "{%0,%1,%2,%3}, {%4,%5,%6,%7}, {%8,%9}, {%0,%1,%2,%3};"
                 : "+f"(c[0]), "+f"(c[1]), "+f"(c[2]), "+f"(c[3])
                 : "r"(a[0]), "r"(a[1]), "r"(a[2]), "r"(a[3]), "r"(b[0]), "r"(b[1]));
}
__device__ __forceinline__ float warp_sum(float v) {
    v += __shfl_xor_sync(0xffffffffu, v, 16);
    v += __shfl_xor_sync(0xffffffffu, v, 8);
    v += __shfl_xor_sync(0xffffffffu, v, 4);
    v += __shfl_xor_sync(0xffffffffu, v, 2);
    v += __shfl_xor_sync(0xffffffffu, v, 1);
    return v;
}
__device__ __forceinline__ int expert_of_group(int g) {
    int task = g / NEe;
    int n = g % NEe;
    return (n < Ss) ? n : Ss + task * Pp + (n - Ss);
}

// ---------------- single-pass fp16 HMMA grouped GEMM — 128x128 tile, 3-stage swizzled pipeline
// A fp16 plane [*,K]; W fp16 plane [N,K].  acc += A*W, fp32 accum.
#define PLANE_B 8192
#define STAGE_B 16384
#define TG_SMEM 66560   // epilogue bounce (128*129*4 = 66048) dominates; 3*16384=49152 fits inside

template <int EPI, int OUT>   // EPI: 0 none, 1 gelu, 2 relu.  OUT: 0 f32, 1 fp16, 2 both
__global__ __launch_bounds__(256, 2)
void tgemm_kernel(const fp16* __restrict__ A, long aStride, int aMode,
                  const fp16* __restrict__ W, long wStride,
                  int wMode, int wMul, int wOff,
                  const float* __restrict__ bias, long bStride,
                  const float* __restrict__ Res, long resStride, int resMode,
                  float* __restrict__ C32, fp16* __restrict__ C16,
                  long cStride, int N, int K, int gBase)
{
    extern __shared__ char dsm[];

    const int g    = blockIdx.z + gBase;
    const int task = g / NEe;
    int wb = 0;
    if (wMode == 1) wb = expert_of_group(g);
    else if (wMode == 2) wb = g;
    const int widx = wb * wMul + wOff;
    const long aoff = (aMode == 1) ? (long)task * aStride : (aMode == 2 ? (long)g * aStride : 0);

    const int tid = threadIdx.x;
    const int blockRow = blockIdx.y * 128;
    const int blockCol = blockIdx.x * 128;

    const fp16* aP = A + aoff + (size_t)blockRow * K;
    const fp16* bP = W + (size_t)widx * wStride + (size_t)blockCol * K;

    const int warp  = tid >> 5, lane = tid & 31;
    const int warpM = warp >> 2, warpN = warp & 3;
    const int grp   = lane >> 2, qp = lane & 3;

    const int lrow = tid >> 2;
    const int lseg = tid & 3;

    const int nch = K >> 5;

    const uint32_t so_h0 = (uint32_t)(lrow * 128 + ((lseg ^ (lrow & 7)) * 16));
    const uint32_t so_h1 = (uint32_t)(lrow * 128 + (((4 + lseg) ^ (lrow & 7)) * 16));

    auto load_chunk = [&](int kc, int s) {
        char* sb = dsm + s * STAGE_B;
        size_t kofs = (size_t)kc * 32 + (size_t)lseg * 8;
        size_t g0 = (size_t)lrow * K + kofs;
        size_t g1 = (size_t)(lrow + 64) * K + kofs;
        cp16(sb +           so_h0, aP + g0);
        cp16(sb +           so_h1, aP + g1);
        cp16(sb + PLANE_B + so_h0, bP + g0);
        cp16(sb + PLANE_B + so_h1, bP + g1);
        asm volatile("cp.async.commit_group;" ::: "memory");
    };

    float acc[4][4][4];
#pragma unroll
    for (int i = 0; i < 4; i++)
#pragma unroll
        for (int j = 0; j < 4; j++)
#pragma unroll
            for (int k = 0; k < 4; k++) acc[i][j][k] = 0.f;

    load_chunk(0, 0);
    load_chunk(1, 1);

    const uint32_t q4 = (uint32_t)(qp * 4);
    auto frago = [&](int row, int gran) -> uint32_t {
        int L = row & 63, hf = row >> 6;
        return (uint32_t)(L * 128 + (((hf * 4 + gran) ^ (L & 7)) * 16)) + q4;
    };

    for (int c = 0; c < nch; ++c) {
        if (c + 2 < nch) asm volatile("cp.async.wait_group 1;" ::: "memory");
        else             asm volatile("cp.async.wait_group 0;" ::: "memory");
        __syncthreads();
        if (c + 2 < nch) load_chunk(c + 2, (c + 2) % 3);

        const char* sb = dsm + (c % 3) * STAGE_B;
        const char* sA = sb;
        const char* sB = sb + PLANE_B;

#pragma unroll
        for (int kt = 0; kt < 2; ++kt) {
            const int gran = kt * 2;
            uint32_t Af[4][4], Bf[4][2];
#pragma unroll
            for (int mt = 0; mt < 4; ++mt) {
                int r0 = warpM * 64 + mt * 16 + grp;
                Af[mt][0] = *(const uint32_t*)(sA + frago(r0, gran));
                Af[mt][1] = *(const uint32_t*)(sA + frago(r0 + 8, gran));
                Af[mt][2] = *(const uint32_t*)(sA + frago(r0, gran + 1));
                Af[mt][3] = *(const uint32_t*)(sA + frago(r0 + 8, gran + 1));
            }
#pragma unroll
            for (int nt = 0; nt < 4; ++nt) {
                int n0 = warpN * 32 + nt * 8 + grp;
                Bf[nt][0] = *(const uint32_t*)(sB + frago(n0, gran));
                Bf[nt][1] = *(const uint32_t*)(sB + frago(n0, gran + 1));
            }
#pragma unroll
            for (int mt = 0; mt < 4; ++mt)
#pragma unroll
                for (int nt = 0; nt < 4; ++nt)
                    mma_f16(acc[mt][nt], Af[mt], Bf[nt]);
        }
    }
    __syncthreads();

    // ---- epilogue
    float* sbuf = reinterpret_cast<float*>(dsm);
#pragma unroll
    for (int mt = 0; mt < 4; ++mt) {
        int r0 = warpM * 64 + mt * 16 + grp;
#pragma unroll
        for (int nt = 0; nt < 4; ++nt) {
            int cb = warpN * 32 + nt * 8 + 2 * qp;
            sbuf[r0 * 129 + cb]       = acc[mt][nt][0];
            sbuf[r0 * 129 + cb + 1]   = acc[mt][nt][1];
            sbuf[(r0+8) * 129 + cb]   = acc[mt][nt][2];
            sbuf[(r0+8) * 129 + cb+1] = acc[mt][nt][3];
        }
    }
    __syncthreads();

    const size_t coff = (size_t)g * cStride;
    const size_t roff = Res ? ((resMode == 1) ? (size_t)task * resStride : (size_t)g * resStride) : 0;

#pragma unroll 4
    for (int it = 0; it < 64; ++it) {
        int idx = it * 256 + tid;
        int rr = idx >> 7, cc = idx & 127;
        int gcol = blockCol + cc;
        float v = sbuf[rr * 129 + cc];
        if (bias) v += bias[(size_t)widx * bStride + gcol];
        size_t rowoff = (size_t)(blockRow + rr) * N + gcol;
        if (Res) v += Res[roff + rowoff];
        if (EPI == 1)      v = 0.5f * v * (1.0f + erff(v * 0.70710678118654752440f));
        else if (EPI == 2) v = fmaxf(v, 0.f);
        size_t o = coff + rowoff;
        if (OUT != 1) C32[o] = v;
        if (OUT >= 1) C16[o] = __float2half_rn(v);
    }
}

// ---------------- attention fusion precompute: Wc = Wv@Wo -> fp16 [N,K]
__global__ void wcomb_kernel(const float* __restrict__ Wv, const float* __restrict__ Wo,
                             fp16* __restrict__ out)
{
    __shared__ float tV[32][33];
    __shared__ float tO[32][33];
    const int z = blockIdx.z;
    const int n0 = blockIdx.x * 32, k0 = blockIdx.y * 32;
    const int tx = threadIdx.x, ty = threadIdx.y;
    const size_t base = (size_t)z * Hh * Hh;
    float acc[4] = {0.f, 0.f, 0.f, 0.f};
    for (int j0 = 0; j0 < Hh; j0 += 32) {
        for (int r = ty; r < 32; r += 8) {
            tV[r][tx] = Wv[base + (size_t)(k0 + r) * Hh + j0 + tx];
            tO[r][tx] = Wo[base + (size_t)(j0 + r) * Hh + n0 + tx];
        }
        __syncthreads();
#pragma unroll
        for (int jj = 0; jj < 32; ++jj) {
            float a = tV[tx][jj];
#pragma unroll
            for (int i = 0; i < 4; ++i)
                acc[i] += a * tO[jj][ty + i * 8];
        }
        __syncthreads();
    }
#pragma unroll
    for (int i = 0; i < 4; ++i) {
        int n = n0 + ty + i * 8;
        out[base + (size_t)n * Hh + k0 + tx] = __float2half_rn(acc[i]);
    }
}

__global__ void bcomb_kernel(const float* __restrict__ bv, const float* __restrict__ Wo,
                             const float* __restrict__ bo, float* __restrict__ bc)
{
    const int z = blockIdx.x;
    const int n = threadIdx.x;
    const float* w = Wo + (size_t)z * Hh * Hh + n;
    const float* b = bv + (size_t)z * Hh;
    float s = bo[(size_t)z * Hh + n];
    for (int k = 0; k < Hh; ++k) s += b[k] * w[(size_t)k * Hh];
    bc[z * Hh + n] = s;
}

// ---------------- weight convert+transpose: f32 [K,N] -> fp16 [N,K]
__global__ void wconv_kernel(const float* __restrict__ src, fp16* __restrict__ out, int K, int N)
{
    __shared__ float tile[32][33];
    const size_t m = (size_t)blockIdx.z * K * N;
    const int n0 = blockIdx.x * 32, k0 = blockIdx.y * 32;
    const int tx = threadIdx.x, ty = threadIdx.y;
    for (int r = ty; r < 32; r += 8)
        tile[r][tx] = src[m + (size_t)(k0 + r) * N + n0 + tx];
    __syncthreads();
    for (int r = ty; r < 32; r += 8)
        out[m + (size_t)(n0 + r) * K + k0 + tx] = __float2half_rn(tile[tx][r]);
}

// ---------------- elementwise f32 -> fp16
__global__ void split_kernel(const float* __restrict__ src, fp16* __restrict__ out, long n)
{
    long i = (long)blockIdx.x * blockDim.x + threadIdx.x;
    if (i < n) out[i] = __float2half_rn(src[i]);
}

// ---------------- fused LayerNorm; reads In (f32), writes OutF32 (optional) + fp16 plane
__global__ void ln_kernel(const float* __restrict__ In, float* __restrict__ OutF32,
                          fp16* __restrict__ Out16,
                          const float* __restrict__ gamma, const float* __restrict__ beta,
                          long gStride, int storeF32)
{
    const int g = blockIdx.y, row = blockIdx.x;
    const int e = expert_of_group(g);
    const long off = ((long)g * Bb + row) * Hh;
    const int t = threadIdx.x;

    float4 hv = *(const float4*)&In[off + t * 4];
    float s = hv.x + hv.y + hv.z + hv.w;
    __shared__ float sh[8];
    const int wid = t >> 5, lane = t & 31;
    s = warp_sum(s);
    if (lane == 0) sh[wid] = s;
    __syncthreads();
    float mean = (sh[0] + sh[1] + sh[2] + sh[3]) * (1.0f / Hh);
    float d0 = hv.x - mean, d1 = hv.y - mean, d2 = hv.z - mean, d3 = hv.w - mean;
    float ss = d0 * d0 + d1 * d1 + d2 * d2 + d3 * d3;
    ss = warp_sum(ss);
    if (lane == 0) sh[4 + wid] = ss;
    __syncthreads();
    float inv = rsqrtf((sh[4] + sh[5] + sh[6] + sh[7]) * (1.0f / Hh) + 1e-5f);

    const float* gm = gamma + (long)e * gStride;
    const float* bt = beta  + (long)e * gStride;
    float4 gv = *(const float4*)&gm[t * 4];
    float4 bv = *(const float4*)&bt[t * 4];
    float o0 = d0 * inv * gv.x + bv.x;
    float o1 = d1 * inv * gv.y + bv.y;
    float o2 = d2 * inv * gv.z + bv.z;
    float o3 = d3 * inv * gv.w + bv.w;
    if (storeF32) *(float4*)&OutF32[off + t * 4] = make_float4(o0, o1, o2, o3);
    __half2 p01 = __floats2half2_rn(o0, o1);
    __half2 p23 = __floats2half2_rn(o2, o3);
    uint2 pk;
    pk.x = *(uint32_t*)&p01;
    pk.y = *(uint32_t*)&p23;
    *(uint2*)&Out16[off + t * 4] = pk;
}

// ---------------- gate stage 1
__global__ void gate1_kernel(const float* __restrict__ x, const float* __restrict__ Wg1,
                             const float* __restrict__ bg1, float* __restrict__ gh)
{
    __shared__ float xs[Dd];
    const int i = blockIdx.y, b = blockIdx.x, t = threadIdx.x;
    const float* xr = x + ((long)i * Bb + b) * Dd;
    for (int k = t; k < Dd; k += 64) xs[k] = xr[k];
    __syncthreads();
    const float* w = Wg1 + (long)i * Dd * Gg + t;
    float s = bg1[i * Gg + t];
#pragma unroll 8
    for (int k = 0; k < Dd; ++k) s += xs[k] * w[(long)k * Gg];
    gh[((long)i * Bb + b) * Gg + t] = fmaxf(s, 0.f);
}

// ---------------- gate stage 2 + softmax
__global__ void gate2_kernel(const float* __restrict__ gh, const float* __restrict__ Wg2,
                             const float* __restrict__ bg2, float* __restrict__ gate)
{
    const int i = blockIdx.y;
    const int row = blockIdx.x * 4 + (threadIdx.x >> 5);
    const int lane = threadIdx.x & 31;
    const float* g1 = gh + ((long)i * Bb + row) * Gg;
    const float x0 = g1[lane], x1 = g1[lane + 32];
    const float* w = Wg2 + (long)i * Gg * NEe;
    float logits[NEe];
#pragma unroll
    for (int n = 0; n < NEe; n++) {
        float p = x0 * w[lane * NEe + n] + x1 * w[(lane + 32) * NEe + n];
        p = warp_sum(p);
        logits[n] = p + bg2[i * NEe + n];
    }
    float m = logits[0];
#pragma unroll
    for (int n = 1; n < NEe; n++) m = fmaxf(m, logits[n]);
    float ssum = 0.f;
#pragma unroll
    for (int n = 0; n < NEe; n++) { logits[n] = expf(logits[n] - m); ssum += logits[n]; }
    float rs = 1.0f / ssum;
    if (lane == 0) {
        float* gp = gate + ((long)i * Bb + row) * NEe;
#pragma unroll
        for (int n = 0; n < NEe; n++) gp[n] = logits[n] * rs;
    }
}

// ---------------- gated combine -> cat fp16
__global__ void combine_kernel(const float* __restrict__ o, const float* __restrict__ gate,
                               fp16* __restrict__ cat16)
{
    long idx = (long)blockIdx.x * blockDim.x + threadIdx.x;
    int d = (int)(idx % Dd);
    long bi = idx / Dd;
    int b = (int)(bi % Bb);
    int i = (int)(bi / Bb);
    const float* gp = gate + ((long)i * Bb + b) * NEe;
    float s = 0.f;
#pragma unroll
    for (int n = 0; n < NEe; n++)
        s += o[(((long)(i * NEe + n)) * Bb + b) * Hh + d] * gp[n];
    cat16[(long)b * (Tt * Dd) + i * Dd + d] = __float2half_rn(s);
}

// ---------------- launch
extern "C" void kernel_launch(void* const* d_in, const int* in_sizes, int n_in,
                              void* d_out, int out_size)
{
    const float* x    = (const float*)d_in[0];
    const float* Win  = (const float*)d_in[1];
    const float* b_in = (const float*)d_in[2];
    const float* Wv   = (const float*)d_in[3];
    const float* bv   = (const float*)d_in[4];
    const float* Wo   = (const float*)d_in[5];
    const float* bo   = (const float*)d_in[6];
    const float* ln1g = (const float*)d_in[7];
    const float* ln1b = (const float*)d_in[8];
    const float* W1   = (const float*)d_in[9];
    const float* b1   = (const float*)d_in[10];
    const float* W2   = (const float*)d_in[11];
    const float* b2   = (const float*)d_in[12];
    const float* ln2g = (const float*)d_in[13];
    const float* ln2b = (const float*)d_in[14];
    const float* lnfg = (const float*)d_in[15];
    const float* lnfb = (const float*)d_in[16];
    const float* Wout = (const float*)d_in[17];
    const float* bout = (const float*)d_in[18];
    const float* Wg1  = (const float*)d_in[19];
    const float* bg1  = (const float*)d_in[20];
    const float* Wg2  = (const float*)d_in[21];
    const float* bg2  = (const float*)d_in[22];
    const float* Wf1  = (const float*)d_in[23];
    const float* bf1  = (const float*)d_in[24];
    const float* Wf2  = (const float*)d_in[25];
    const float* bf2  = (const float*)d_in[26];

    fp16 *wWin, *wWc, *wW1, *wW2, *wWout, *wWf1, *wWf2;
    fp16 *x16, *h16, *f16, *cat16, *fu16;
    float *h32, *t232, *o32, *gh, *gate, *bc;
    cudaGetSymbolAddress((void**)&wWin, g_wWin);
    cudaGetSymbolAddress((void**)&wWc,  g_wWc);
    cudaGetSymbolAddress((void**)&wW1,  g_wW1);
    cudaGetSymbolAddress((void**)&wW2,  g_wW2);
    cudaGetSymbolAddress((void**)&wWout,g_wWout);
    cudaGetSymbolAddress((void**)&wWf1, g_wWf1);
    cudaGetSymbolAddress((void**)&wWf2, g_wWf2);
    cudaGetSymbolAddress((void**)&x16, g_x16);
    cudaGetSymbolAddress((void**)&h16, g_h16);
    cudaGetSymbolAddress((void**)&f16, g_f16);
    cudaGetSymbolAddress((void**)&cat16, g_cat16);
    cudaGetSymbolAddress((void**)&fu16, g_fuse16);
    cudaGetSymbolAddress((void**)&h32, g_h32);  cudaGetSymbolAddress((void**)&t232, g_t232);
    cudaGetSymbolAddress((void**)&o32, g_o32);  cudaGetSymbolAddress((void**)&gh, g_gh);
    cudaGetSymbolAddress((void**)&gate, g_gate); cudaGetSymbolAddress((void**)&bc, g_bc);

    cudaFuncSetAttribute((const void*)tgemm_kernel<0,0>, cudaFuncAttributeMaxDynamicSharedMemorySize, TG_SMEM);
    cudaFuncSetAttribute((const void*)tgemm_kernel<0,1>, cudaFuncAttributeMaxDynamicSharedMemorySize, TG_SMEM);
    cudaFuncSetAttribute((const void*)tgemm_kernel<0,2>, cudaFuncAttributeMaxDynamicSharedMemorySize, TG_SMEM);
    cudaFuncSetAttribute((const void*)tgemm_kernel<1,1>, cudaFuncAttributeMaxDynamicSharedMemorySize, TG_SMEM);
    cudaFuncSetAttribute((const void*)tgemm_kernel<2,1>, cudaFuncAttributeMaxDynamicSharedMemorySize, TG_SMEM);

    const long GB = (long)Bb * Hh;
    const long GF = (long)Bb * Ff;
    dim3 blk(256);
    dim3 gHH(Hh / 128, Bb / 128, NG);
    dim3 gHHh(Hh / 128, Bb / 128, 9);
    dim3 gHF(Ff / 128, Bb / 128, NG);
    dim3 lnG(Bb, NG);
    dim3 cb(32, 8);

    cudaStream_t s0 = 0;
    cudaStream_t s2;
    cudaStreamCreateWithFlags(&s2, cudaStreamNonBlocking);
    cudaEvent_t eFork, eJoin;
    cudaEventCreateWithFlags(&eFork, cudaEventDisableTiming);
    cudaEventCreateWithFlags(&eJoin, cudaEventDisableTiming);

    cudaEventRecord(eFork, s0);
    cudaStreamWaitEvent(s2, eFork, 0);

    // main stream: deps of input GEMM, then input GEMM (ncu capture idx 3/4)
    wconv_kernel<<<dim3(Hh/32, Dd/32, 10), cb, 0, s0>>>(Win, wWin, Dd, Hh);
    long nx = (long)Tt * Bb * Dd;
    split_kernel<<<(unsigned)((nx + 255) / 256), 256, 0, s0>>>(x, x16, nx);
    tgemm_kernel<0,2><<<gHHh, blk, TG_SMEM, s0>>>(x16, (long)Bb * Dd, 1,
        wWin, (long)Dd * Hh, 1, 1, 0, b_in, Hh,
        nullptr, 0, 0, h32, h16, GB, Hh, Dd, 0);
    tgemm_kernel<0,2><<<gHHh, blk, TG_SMEM, s0>>>(x16, (long)Bb * Dd, 1,
        wWin, (long)Dd * Hh, 1, 1, 0, b_in, Hh,
        nullptr, 0, 0, h32, h16, GB, Hh, Dd, 9);

    // side stream: remaining prepass overlaps input GEMM
    wcomb_kernel<<<dim3(Hh/32, Hh/32, 20), cb, 0, s2>>>(Wv, Wo, wWc);
    bcomb_kernel<<<20, Hh, 0, s2>>>(bv, Wo, bo, bc);
    wconv_kernel<<<dim3(Ff/32, Hh/32, 20), cb, 0, s2>>>(W1,   wW1,   Hh, Ff);
    wconv_kernel<<<dim3(Hh/32, Ff/32, 20), cb, 0, s2>>>(W2,   wW2,   Ff, Hh);
    wconv_kernel<<<dim3(Dd/32, Hh/32, 10), cb, 0, s2>>>(Wout, wWout, Hh, Dd);
    wconv_kernel<<<dim3((2*Dd)/32, (Tt*Dd)/32, 1), cb, 0, s2>>>(Wf1, wWf1, Tt*Dd, 2*Dd);
    wconv_kernel<<<dim3(Dd/32, (2*Dd)/32, 1), cb, 0, s2>>>(Wf2, wWf2, 2*Dd, Dd);
    gate1_kernel<<<dim3(Bb, Tt), 64, 0, s2>>>(x, Wg1, bg1, gh);
    gate2_kernel<<<dim3(Bb / 4, Tt), 128, 0, s2>>>(gh, Wg2, bg2, gate);
    cudaEventRecord(eJoin, s2);
    cudaStreamWaitEvent(s0, eJoin, 0);

    for (int l = 0; l < Ll; l++) {
        // fused attention + residual: t232 = h + (h @ Wc + bc)
        tgemm_kernel<0,0><<<gHH, blk, TG_SMEM, s0>>>(h16, GB, 2,
            wWc, (long)Hh * Hh, 1, Ll, l, bc, Hh,
            h32, GB, 2, t232, nullptr, GB, Hh, Hh, 0);
        ln_kernel<<<lnG, 128, 0, s0>>>(t232, h32, h16, ln1g + (long)l * Hh, ln1b + (long)l * Hh, (long)Ll * Hh, 1);
        tgemm_kernel<1,1><<<gHF, blk, TG_SMEM, s0>>>(h16, GB, 2,
            wW1, (long)Hh * Ff, 1, Ll, l, b1, Ff,
            nullptr, 0, 0, nullptr, f16, GF, Ff, Hh, 0);
        // fused FFN + residual: t232 = h + (f @ W2 + b2)
        tgemm_kernel<0,0><<<gHH, blk, TG_SMEM, s0>>>(f16, GF, 2,
            wW2, (long)Ff * Hh, 1, Ll, l, b2, Hh,
            h32, GB, 2, t232, nullptr, GB, Hh, Ff, 0);
        ln_kernel<<<lnG, 128, 0, s0>>>(t232, h32, h16, ln2g + (long)l * Hh, ln2b + (long)l * Hh, (long)Ll * Hh, 1);
    }

    ln_kernel<<<lnG, 128, 0, s0>>>(h32, h32, h16, lnfg, lnfb, (long)Hh, 0);

    tgemm_kernel<0,0><<<gHH, blk, TG_SMEM, s0>>>(h16, GB, 2,
        wWout, (long)Hh * Dd, 1, 1, 0, bout, Dd,
        x, (long)Bb * Dd, 1, o32, nullptr, GB, Dd, Hh, 0);

    combine_kernel<<<(unsigned)(((long)Tt * Bb * Dd) / 256), 256, 0, s0>>>(o32, gate, cat16);

    tgemm_kernel<2,1><<<dim3((2*Dd)/128, Bb/128, 1), blk, TG_SMEM, s0>>>(cat16, 0, 0,
        wWf1, 0, 0, 1, 0, bf1, 0,
        nullptr, 0, 0, nullptr, fu16, 0, 2*Dd, Tt*Dd, 0);
    tgemm_kernel<0,0><<<dim3(Dd/128, Bb/128, 1), blk, TG_SMEM, s0>>>(fu16, 0, 0,
        wWf2, 0, 0, 1, 0, bf2, 0,
        nullptr, 0, 0, (float*)d_out, nullptr, 0, Dd, 2*Dd, 0);

    cudaEventDestroy(eFork);
    cudaEventDestroy(eJoin);
    cudaStreamDestroy(s2);
}